// round 11
// baseline (speedup 1.0000x reference)
#include <cuda_runtime.h>
#include <cuda_fp16.h>
#include <math.h>
#include <stdint.h>

#define S_LEN   8192
#define BATCH   4
#define DMODEL  1024
#define NROWS   (BATCH * S_LEN)   // 32768
#define NHEADS  16
#define DHEAD   64

// Scratch (device globals: allocation-free per harness rules)
__device__ float  g_q[(size_t)NROWS * DMODEL];    // fp32 Q features
__device__ float  g_k[(size_t)NROWS * DMODEL];    // fp32 K features
__device__ float  g_v[(size_t)NROWS * DMODEL];    // fp32 V
__device__ __half g_hq[(size_t)NROWS * DMODEL];   // fp16-rounded inputs
__device__ __half g_hk[(size_t)NROWS * DMODEL];
__device__ __half g_hv[(size_t)NROWS * DMODEL];
__device__ __half g_hattn[(size_t)NROWS * DMODEL];
__device__ __half g_hw[4][DMODEL * DMODEL];       // fp16-rounded weights
__device__ float  g_kv[BATCH * NHEADS * DHEAD * DHEAD];   // [b,h,dv,dk]
__device__ float  g_ksum[BATCH * NHEADS * DHEAD];

// ---------------------------------------------------------------------------
// helpers
// ---------------------------------------------------------------------------
__device__ __forceinline__ void mma_fp16(float* c, const unsigned* a, const unsigned* b) {
    asm volatile(
        "mma.sync.aligned.m16n8k16.row.col.f32.f16.f16.f32 "
        "{%0,%1,%2,%3}, {%4,%5,%6,%7}, {%8,%9}, {%0,%1,%2,%3};"
        : "+f"(c[0]), "+f"(c[1]), "+f"(c[2]), "+f"(c[3])
        : "r"(a[0]), "r"(a[1]), "r"(a[2]), "r"(a[3]), "r"(b[0]), "r"(b[1]));
}

__device__ __forceinline__ void cp_async16(unsigned smem_addr, const void* gptr) {
    asm volatile("cp.async.cg.shared.global [%0], [%1], 16;"
                 :: "r"(smem_addr), "l"(gptr));
}
__device__ __forceinline__ void cp_commit() {
    asm volatile("cp.async.commit_group;");
}
template <int N>
__device__ __forceinline__ void cp_wait() {
    asm volatile("cp.async.wait_group %0;" :: "n"(N));
}

// ---------------------------------------------------------------------------
// Elementwise fp16 rounding pass (float4 -> 4 halves)
// ---------------------------------------------------------------------------
__global__ void round_fp16_kernel(const float* __restrict__ in,
                                  __half* __restrict__ out, int n4) {
    int i = blockIdx.x * blockDim.x + threadIdx.x;
    if (i < n4) {
        float4 v = ((const float4*)in)[i];
        __half2 h01 = __floats2half2_rn(v.x, v.y);
        __half2 h23 = __floats2half2_rn(v.z, v.w);
        __half2* o = (__half2*)(out + (size_t)i * 4);
        o[0] = h01; o[1] = h23;
    }
}

__global__ void zero_kernel(float* p, int n) {
    int i = blockIdx.x * blockDim.x + threadIdx.x;
    if (i < n) p[i] = 0.0f;
}

// ---------------------------------------------------------------------------
// fp16 GEMM: C[M,1024] = A[M,1024] @ W[1024,1024]^T + bias, optional elu+1.
// 256 threads, 8 warps (2x4), warp tile 64x32.
// Double-chunk pipeline: each step moves 64 k (2 subtiles of 32), 2-stage
// double buffer, ONE barrier per step:
//   wait<0>; __syncthreads(); fill(d+1); commit; compute(2 subtiles)
// Overwrite safety: fill(d+1) targets the stage read at step d-1; every warp
// passed compute(d-1) before this step's barrier.
// Subtile layout unchanged (SPADH=48, conflict-free LDS.64, k-reassignment:
// thread tg carries physical k = {4tg..4tg+3} for both operands).
// ---------------------------------------------------------------------------
#define BM 128
#define BN 128
#define BKH 32                    // k halves per subchunk
#define SPADH 48                  // halves per smem row (96B)
#define TILEH (BM * SPADH)        // 6144 halves = 12288 B per subtile
#define NSUB 4                    // 2 stages x 2 subtiles per operand
#define GEMM_SMEM_BYTES (2 * NSUB * TILEH * 2)   // 98304 B

template <int EPI>
__global__ void __launch_bounds__(256, 2)
gemm_fp16_kernel(const __half* __restrict__ A, const __half* __restrict__ W,
                 const float* __restrict__ bias, float* __restrict__ C) {
    extern __shared__ __half sh[];            // [A: 4 subtiles][B: 4 subtiles]
    __half* Asm = sh;
    __half* Bsm = sh + NSUB * TILEH;

    const int tid  = threadIdx.x;
    const int lane = tid & 31;
    const int warp = tid >> 5;
    const int wm   = (warp & 1) * 64;
    const int wn   = (warp >> 1) * 32;
    const int m0   = blockIdx.y * BM;
    const int n0   = blockIdx.x * BN;
    const int g    = lane >> 2;
    const int tg   = lane & 3;

    unsigned sbase = (unsigned)__cvta_generic_to_shared(sh);

    float acc[4][4][4];
#pragma unroll
    for (int mt = 0; mt < 4; mt++)
#pragma unroll
        for (int nt = 0; nt < 4; nt++)
#pragma unroll
            for (int i = 0; i < 4; i++) acc[mt][nt][i] = 0.0f;

    const int r0  = tid >> 2;          // rows r0, r0+64
    const int kc  = (tid & 3) * 8;
    const __half* Ap = A + (size_t)(m0 + r0) * DMODEL + kc;
    const __half* Wp = W + (size_t)(n0 + r0) * DMODEL + kc;
    const unsigned a_d0 = sbase + (r0 * SPADH + kc) * 2;
    const unsigned a_d1 = sbase + ((r0 + 64) * SPADH + kc) * 2;
    const unsigned b_d0 = a_d0 + NSUB * TILEH * 2;
    const unsigned b_d1 = a_d1 + NSUB * TILEH * 2;

    const int ND = DMODEL / (2 * BKH);   // 16 double-chunk steps

    // fill double-chunk d (subchunks 2d, 2d+1) into stage d&1
    auto fill = [&](int d) {
        const int stage = d & 1;
#pragma unroll
        for (int sub = 0; sub < 2; sub++) {
            const int c = 2 * d + sub;
            const unsigned so = (unsigned)(stage * 2 + sub) * TILEH * 2;
            const __half* Apn = Ap + c * BKH;
            const __half* Wpn = Wp + c * BKH;
            cp_async16(a_d0 + so, Apn);
            cp_async16(a_d1 + so, Apn + (size_t)64 * DMODEL);
            cp_async16(b_d0 + so, Wpn);
            cp_async16(b_d1 + so, Wpn + (size_t)64 * DMODEL);
        }
    };

    fill(0); cp_commit();

    for (int d = 0; d < ND; d++) {
        cp_wait<0>();          // double-chunk d resident (this thread)
        __syncthreads();       // publish fills; all warps done with stage (d-1)&1

        if (d + 1 < ND) { fill(d + 1); cp_commit(); }

        const int stage = d & 1;
#pragma unroll
        for (int sub = 0; sub < 2; sub++) {
            const __half* Ab = Asm + (stage * 2 + sub) * TILEH;
            const __half* Bb = Bsm + (stage * 2 + sub) * TILEH;
#pragma unroll
            for (int ks = 0; ks < 2; ks++) {
                const int kk = ks * 16 + 4 * tg;
                unsigned a[4][4], b[4][2];
#pragma unroll
                for (int mt = 0; mt < 4; mt++) {
                    int base = (wm + mt * 16 + g) * SPADH + kk;
                    uint2 lo = *(const uint2*)&Ab[base];
                    uint2 hi = *(const uint2*)&Ab[base + 8 * SPADH];
                    a[mt][0] = lo.x; a[mt][1] = hi.x; a[mt][2] = lo.y; a[mt][3] = hi.y;
                }
#pragma unroll
                for (int nt = 0; nt < 4; nt++) {
                    uint2 bb = *(const uint2*)&Bb[(wn + nt * 8 + g) * SPADH + kk];
                    b[nt][0] = bb.x; b[nt][1] = bb.y;
                }
#pragma unroll
                for (int mt = 0; mt < 4; mt++)
#pragma unroll
                    for (int nt = 0; nt < 4; nt++)
                        mma_fp16(acc[mt][nt], a[mt], b[nt]);
            }
        }
    }

    // epilogue: bias + optional elu(x)+1, float2 stores
#pragma unroll
    for (int mt = 0; mt < 4; mt++) {
#pragma unroll
        for (int nt = 0; nt < 4; nt++) {
            int row = m0 + wm + mt * 16 + g;
            int col = n0 + wn + nt * 8 + 2 * tg;
            float bv0 = bias[col];
            float bv1 = bias[col + 1];
            float v00 = acc[mt][nt][0] + bv0;
            float v01 = acc[mt][nt][1] + bv1;
            float v10 = acc[mt][nt][2] + bv0;
            float v11 = acc[mt][nt][3] + bv1;
            if (EPI) {
                v00 = (v00 > 0.0f) ? v00 + 1.0f : expf(v00);
                v01 = (v01 > 0.0f) ? v01 + 1.0f : expf(v01);
                v10 = (v10 > 0.0f) ? v10 + 1.0f : expf(v10);
                v11 = (v11 > 0.0f) ? v11 + 1.0f : expf(v11);
            }
            *(float2*)&C[(size_t)row * DMODEL + col]       = make_float2(v00, v01);
            *(float2*)&C[(size_t)(row + 8) * DMODEL + col] = make_float2(v10, v11);
        }
    }
}

// ---------------------------------------------------------------------------
// KV chain: kv[b,h,i,j] = sum_s V[b,s,h,i] * K[b,s,h,j];  ksum[b,h,j] = sum_s K
// ---------------------------------------------------------------------------
__global__ void __launch_bounds__(256)
kv_kernel(const float* __restrict__ K, const float* __restrict__ V,
          float* __restrict__ kv, float* __restrict__ ksum) {
    const int bh = blockIdx.x;
    const int b  = bh / NHEADS;
    const int h  = bh % NHEADS;
    const int tid = threadIdx.x;
    const int ty  = tid >> 4;
    const int tx  = tid & 15;

    __shared__ float Ks[16][64];
    __shared__ float Vs[16][64];

    float acc[4][4];
#pragma unroll
    for (int i = 0; i < 4; i++)
#pragma unroll
        for (int j = 0; j < 4; j++) acc[i][j] = 0.0f;
    float ks_acc = 0.0f;

    const float* Kbase = K + (size_t)b * S_LEN * DMODEL + h * DHEAD;
    const float* Vbase = V + (size_t)b * S_LEN * DMODEL + h * DHEAD;
    const int s0 = blockIdx.y * (S_LEN / 8);

    for (int s = s0; s < s0 + (S_LEN / 8); s += 16) {
        __syncthreads();
        {
            int r  = tid >> 4;
            int c4 = (tid & 15) << 2;
            *(float4*)&Ks[r][c4] = *(const float4*)&Kbase[(size_t)(s + r) * DMODEL + c4];
            *(float4*)&Vs[r][c4] = *(const float4*)&Vbase[(size_t)(s + r) * DMODEL + c4];
        }
        __syncthreads();
        if (tid < 64) {
#pragma unroll
            for (int ss = 0; ss < 16; ss++) ks_acc += Ks[ss][tid];
        }
#pragma unroll
        for (int ss = 0; ss < 16; ss++) {
            float vr[4], kr[4];
#pragma unroll
            for (int i = 0; i < 4; i++) vr[i] = Vs[ss][ty * 4 + i];
#pragma unroll
            for (int j = 0; j < 4; j++) kr[j] = Ks[ss][tx * 4 + j];
#pragma unroll
            for (int i = 0; i < 4; i++)
#pragma unroll
                for (int j = 0; j < 4; j++) acc[i][j] += vr[i] * kr[j];
        }
    }

    float* kvbh = kv + (size_t)bh * DHEAD * DHEAD;
#pragma unroll
    for (int i = 0; i < 4; i++)
#pragma unroll
        for (int j = 0; j < 4; j++)
            atomicAdd(&kvbh[(ty * 4 + i) * DHEAD + tx * 4 + j], acc[i][j]);
    if (tid < 64) atomicAdd(&ksum[bh * DHEAD + tid], ks_acc);
}

// ---------------------------------------------------------------------------
// Attention apply; output rounded to fp16 for the final GEMM
// ---------------------------------------------------------------------------
__global__ void __launch_bounds__(128)
attn_kernel(const float* __restrict__ Q, const float* __restrict__ kv,
            const float* __restrict__ ksum, __half* __restrict__ attn) {
    const int h   = blockIdx.y;
    const int row = blockIdx.x * 128 + threadIdx.x;
    const int b   = row / S_LEN;

    __shared__ float kvs[64][64];
    __shared__ float kss[64];

    const float* kvsrc = kv + (size_t)(b * NHEADS + h) * DHEAD * DHEAD;
    for (int i = threadIdx.x; i < (DHEAD * DHEAD) / 4; i += 128)
        ((float4*)kvs)[i] = ((const float4*)kvsrc)[i];
    if (threadIdx.x < 64) kss[threadIdx.x] = ksum[(b * NHEADS + h) * DHEAD + threadIdx.x];
    __syncthreads();

    float q[64];
    const float* qp = Q + (size_t)row * DMODEL + h * DHEAD;
#pragma unroll
    for (int i = 0; i < 16; i++) ((float4*)q)[i] = ((const float4*)qp)[i];

    float nd = 0.0f;
#pragma unroll
    for (int d = 0; d < 64; d++) nd += q[d] * kss[d];
    const float norm = 1.0f / (nd + 1e-6f);

    __half* op = attn + (size_t)row * DMODEL + h * DHEAD;
    for (int i0 = 0; i0 < 64; i0 += 4) {
        float out[4];
#pragma unroll
        for (int u = 0; u < 4; u++) {
            float s = 0.0f;
            const float4* kv4 = (const float4*)kvs[i0 + u];
#pragma unroll
            for (int d4 = 0; d4 < 16; d4++) {
                float4 kvv = kv4[d4];
                s += q[4*d4] * kvv.x + q[4*d4+1] * kvv.y
                   + q[4*d4+2] * kvv.z + q[4*d4+3] * kvv.w;
            }
            out[u] = s * norm;
        }
        __half2 h01 = __floats2half2_rn(out[0], out[1]);
        __half2 h23 = __floats2half2_rn(out[2], out[3]);
        *(__half2*)&op[i0]     = h01;
        *(__half2*)&op[i0 + 2] = h23;
    }
}

// ---------------------------------------------------------------------------
// Launch
// ---------------------------------------------------------------------------
extern "C" void kernel_launch(void* const* d_in, const int* in_sizes, int n_in,
                              void* d_out, int out_size) {
    const float* query = (const float*)d_in[0];
    const float* key_  = (const float*)d_in[1];
    const float* value = (const float*)d_in[2];
    const float* Wq = (const float*)d_in[3];
    const float* bq = (const float*)d_in[4];
    const float* Wk = (const float*)d_in[5];
    const float* bk = (const float*)d_in[6];
    const float* Wv = (const float*)d_in[7];
    const float* bv = (const float*)d_in[8];
    const float* Wo = (const float*)d_in[9];
    const float* bo = (const float*)d_in[10];
    float* out = (float*)d_out;

    float *qf, *kf, *vf, *kv, *ks;
    __half *hq, *hk, *hv, *hattn, *hw;
    cudaGetSymbolAddress((void**)&qf,    g_q);
    cudaGetSymbolAddress((void**)&kf,    g_k);
    cudaGetSymbolAddress((void**)&vf,    g_v);
    cudaGetSymbolAddress((void**)&kv,    g_kv);
    cudaGetSymbolAddress((void**)&ks,    g_ksum);
    cudaGetSymbolAddress((void**)&hq,    g_hq);
    cudaGetSymbolAddress((void**)&hk,    g_hk);
    cudaGetSymbolAddress((void**)&hv,    g_hv);
    cudaGetSymbolAddress((void**)&hattn, g_hattn);
    cudaGetSymbolAddress((void**)&hw,    g_hw);
    __half* hwq = hw;
    __half* hwk = hw + (size_t)DMODEL * DMODEL;
    __half* hwv = hw + (size_t)2 * DMODEL * DMODEL;
    __half* hwo = hw + (size_t)3 * DMODEL * DMODEL;

    static int smem_set = 0;
    if (!smem_set) {
        cudaFuncSetAttribute(gemm_fp16_kernel<1>,
                             cudaFuncAttributeMaxDynamicSharedMemorySize, GEMM_SMEM_BYTES);
        cudaFuncSetAttribute(gemm_fp16_kernel<0>,
                             cudaFuncAttributeMaxDynamicSharedMemorySize, GEMM_SMEM_BYTES);
        smem_set = 1;
    }

    // fp16 pre-rounding passes
    const int N4_IN = (NROWS * DMODEL) / 4;
    const int N4_W  = (DMODEL * DMODEL) / 4;
    round_fp16_kernel<<<N4_IN / 256, 256>>>(query, hq, N4_IN);
    round_fp16_kernel<<<N4_IN / 256, 256>>>(key_,  hk, N4_IN);
    round_fp16_kernel<<<N4_IN / 256, 256>>>(value, hv, N4_IN);
    round_fp16_kernel<<<N4_W / 256, 256>>>(Wq, hwq, N4_W);
    round_fp16_kernel<<<N4_W / 256, 256>>>(Wk, hwk, N4_W);
    round_fp16_kernel<<<N4_W / 256, 256>>>(Wv, hwv, N4_W);
    round_fp16_kernel<<<N4_W / 256, 256>>>(Wo, hwo, N4_W);

    // zero accumulators for atomics
    zero_kernel<<<(BATCH * NHEADS * DHEAD * DHEAD + 255) / 256, 256>>>(kv, BATCH * NHEADS * DHEAD * DHEAD);
    zero_kernel<<<(BATCH * NHEADS * DHEAD + 255) / 256, 256>>>(ks, BATCH * NHEADS * DHEAD);

    dim3 gemm_grid(DMODEL / BN, NROWS / BM);  // (8, 256)
    gemm_fp16_kernel<1><<<gemm_grid, 256, GEMM_SMEM_BYTES>>>(hq, hwq, bq, qf);
    gemm_fp16_kernel<1><<<gemm_grid, 256, GEMM_SMEM_BYTES>>>(hk, hwk, bk, kf);
    gemm_fp16_kernel<0><<<gemm_grid, 256, GEMM_SMEM_BYTES>>>(hv, hwv, bv, vf);

    kv_kernel<<<dim3(BATCH * NHEADS, 8), 256>>>(kf, vf, kv, ks);

    attn_kernel<<<dim3(NROWS / 128, NHEADS), 128>>>(qf, kv, ks, hattn);

    gemm_fp16_kernel<0><<<gemm_grid, 256, GEMM_SMEM_BYTES>>>(hattn, hwo, bo, out);
}

// round 12
// speedup vs baseline: 1.0348x; 1.0348x over previous
#include <cuda_runtime.h>
#include <cuda_fp16.h>
#include <math.h>
#include <stdint.h>

#define S_LEN   8192
#define BATCH   4
#define DMODEL  1024
#define NROWS   (BATCH * S_LEN)   // 32768
#define NHEADS  16
#define DHEAD   64

// Scratch (device globals: allocation-free per harness rules)
__device__ __half g_hqf[(size_t)NROWS * DMODEL];  // fp16 Q features
__device__ __half g_hkf[(size_t)NROWS * DMODEL];  // fp16 K features
__device__ __half g_hvf[(size_t)NROWS * DMODEL];  // fp16 V features
__device__ __half g_hq[(size_t)NROWS * DMODEL];   // fp16-rounded inputs
__device__ __half g_hk[(size_t)NROWS * DMODEL];
__device__ __half g_hv[(size_t)NROWS * DMODEL];
__device__ __half g_hattn[(size_t)NROWS * DMODEL];
__device__ __half g_hw[4][DMODEL * DMODEL];       // fp16-rounded weights
__device__ float  g_kv[BATCH * NHEADS * DHEAD * DHEAD];   // [b,h,dv,dk]
__device__ float  g_ksum[BATCH * NHEADS * DHEAD];

// ---------------------------------------------------------------------------
// helpers
// ---------------------------------------------------------------------------
__device__ __forceinline__ void mma_fp16(float* c, const unsigned* a, const unsigned* b) {
    asm volatile(
        "mma.sync.aligned.m16n8k16.row.col.f32.f16.f16.f32 "
        "{%0,%1,%2,%3}, {%4,%5,%6,%7}, {%8,%9}, {%0,%1,%2,%3};"
        : "+f"(c[0]), "+f"(c[1]), "+f"(c[2]), "+f"(c[3])
        : "r"(a[0]), "r"(a[1]), "r"(a[2]), "r"(a[3]), "r"(b[0]), "r"(b[1]));
}

__device__ __forceinline__ void cp_async16(unsigned smem_addr, const void* gptr) {
    asm volatile("cp.async.cg.shared.global [%0], [%1], 16;"
                 :: "r"(smem_addr), "l"(gptr));
}
__device__ __forceinline__ void cp_commit() {
    asm volatile("cp.async.commit_group;");
}
template <int N>
__device__ __forceinline__ void cp_wait() {
    asm volatile("cp.async.wait_group %0;" :: "n"(N));
}

// ---------------------------------------------------------------------------
// Elementwise fp16 rounding pass (float4 -> 4 halves)
// ---------------------------------------------------------------------------
__global__ void round_fp16_kernel(const float* __restrict__ in,
                                  __half* __restrict__ out, int n4) {
    int i = blockIdx.x * blockDim.x + threadIdx.x;
    if (i < n4) {
        float4 v = ((const float4*)in)[i];
        __half2 h01 = __floats2half2_rn(v.x, v.y);
        __half2 h23 = __floats2half2_rn(v.z, v.w);
        __half2* o = (__half2*)(out + (size_t)i * 4);
        o[0] = h01; o[1] = h23;
    }
}

__global__ void zero_kernel(float* p, int n) {
    int i = blockIdx.x * blockDim.x + threadIdx.x;
    if (i < n) p[i] = 0.0f;
}

// ---------------------------------------------------------------------------
// fp16 GEMM (R10 proven config): C = A @ W^T + bias, optional elu+1.
// Output fp32 (OUTH=0) or fp16 (OUTH=1).
// 256 threads, 8 warps (2x4), warp tile 64x32.
// 3-stage cp.async pipeline, ONE barrier per k-chunk:
//   wait<1>; __syncthreads(); fill(kt+2); commit; compute(kt)
// k-reassignment: thread tg carries physical k = {4tg..4tg+3} for both
// operands -> conflict-free LDS.64 with SPADH=48.
// ---------------------------------------------------------------------------
#define BM 128
#define BN 128
#define BKH 32                    // k halves per chunk
#define SPADH 48                  // halves per smem row (96B)
#define TILEH (BM * SPADH)        // 6144 halves = 12288 B
#define NSTAGE 3
#define GEMM_SMEM_BYTES (2 * NSTAGE * TILEH * 2)   // 73728 B

template <int EPI, int OUTH>
__global__ void __launch_bounds__(256, 2)
gemm_fp16_kernel(const __half* __restrict__ A, const __half* __restrict__ W,
                 const float* __restrict__ bias, void* __restrict__ Cv) {
    extern __shared__ __half sh[];            // [A0,A1,A2,B0,B1,B2]
    __half* Asm = sh;
    __half* Bsm = sh + NSTAGE * TILEH;

    const int tid  = threadIdx.x;
    const int lane = tid & 31;
    const int warp = tid >> 5;
    const int wm   = (warp & 1) * 64;
    const int wn   = (warp >> 1) * 32;
    const int m0   = blockIdx.y * BM;
    const int n0   = blockIdx.x * BN;
    const int g    = lane >> 2;
    const int tg   = lane & 3;

    unsigned sbase = (unsigned)__cvta_generic_to_shared(sh);

    float acc[4][4][4];
#pragma unroll
    for (int mt = 0; mt < 4; mt++)
#pragma unroll
        for (int nt = 0; nt < 4; nt++)
#pragma unroll
            for (int i = 0; i < 4; i++) acc[mt][nt][i] = 0.0f;

    const int r0  = tid >> 2;          // rows r0, r0+64
    const int kc  = (tid & 3) * 8;
    const __half* Ap = A + (size_t)(m0 + r0) * DMODEL + kc;
    const __half* Wp = W + (size_t)(n0 + r0) * DMODEL + kc;
    const unsigned a_d0 = sbase + (r0 * SPADH + kc) * 2;
    const unsigned a_d1 = sbase + ((r0 + 64) * SPADH + kc) * 2;
    const unsigned b_d0 = a_d0 + NSTAGE * TILEH * 2;
    const unsigned b_d1 = a_d1 + NSTAGE * TILEH * 2;

    const int NK = DMODEL / BKH;   // 32 chunks

    auto fill = [&](int c) {
        const unsigned so = (unsigned)(c % NSTAGE) * TILEH * 2;
        const __half* Apn = Ap + c * BKH;
        const __half* Wpn = Wp + c * BKH;
        cp_async16(a_d0 + so, Apn);
        cp_async16(a_d1 + so, Apn + (size_t)64 * DMODEL);
        cp_async16(b_d0 + so, Wpn);
        cp_async16(b_d1 + so, Wpn + (size_t)64 * DMODEL);
    };

    fill(0); cp_commit();
    fill(1); cp_commit();

    for (int kt = 0; kt < NK; kt++) {
        cp_wait<1>();
        __syncthreads();

        if (kt + 2 < NK) fill(kt + 2);
        cp_commit();

        const int buf = kt % NSTAGE;
        const __half* Ab = Asm + buf * TILEH;
        const __half* Bb = Bsm + buf * TILEH;
#pragma unroll
        for (int ks = 0; ks < 2; ks++) {
            const int kk = ks * 16 + 4 * tg;
            unsigned a[4][4], b[4][2];
#pragma unroll
            for (int mt = 0; mt < 4; mt++) {
                int base = (wm + mt * 16 + g) * SPADH + kk;
                uint2 lo = *(const uint2*)&Ab[base];
                uint2 hi = *(const uint2*)&Ab[base + 8 * SPADH];
                a[mt][0] = lo.x; a[mt][1] = hi.x; a[mt][2] = lo.y; a[mt][3] = hi.y;
            }
#pragma unroll
            for (int nt = 0; nt < 4; nt++) {
                uint2 bb = *(const uint2*)&Bb[(wn + nt * 8 + g) * SPADH + kk];
                b[nt][0] = bb.x; b[nt][1] = bb.y;
            }
#pragma unroll
            for (int mt = 0; mt < 4; mt++)
#pragma unroll
                for (int nt = 0; nt < 4; nt++)
                    mma_fp16(acc[mt][nt], a[mt], b[nt]);
        }
    }

    // epilogue: bias + optional elu(x)+1
#pragma unroll
    for (int mt = 0; mt < 4; mt++) {
#pragma unroll
        for (int nt = 0; nt < 4; nt++) {
            int row = m0 + wm + mt * 16 + g;
            int col = n0 + wn + nt * 8 + 2 * tg;
            float bv0 = bias[col];
            float bv1 = bias[col + 1];
            float v00 = acc[mt][nt][0] + bv0;
            float v01 = acc[mt][nt][1] + bv1;
            float v10 = acc[mt][nt][2] + bv0;
            float v11 = acc[mt][nt][3] + bv1;
            if (EPI) {
                v00 = (v00 > 0.0f) ? v00 + 1.0f : expf(v00);
                v01 = (v01 > 0.0f) ? v01 + 1.0f : expf(v01);
                v10 = (v10 > 0.0f) ? v10 + 1.0f : expf(v10);
                v11 = (v11 > 0.0f) ? v11 + 1.0f : expf(v11);
            }
            if (OUTH) {
                __half* C = (__half*)Cv;
                *(__half2*)&C[(size_t)row * DMODEL + col]       = __floats2half2_rn(v00, v01);
                *(__half2*)&C[(size_t)(row + 8) * DMODEL + col] = __floats2half2_rn(v10, v11);
            } else {
                float* C = (float*)Cv;
                *(float2*)&C[(size_t)row * DMODEL + col]       = make_float2(v00, v01);
                *(float2*)&C[(size_t)(row + 8) * DMODEL + col] = make_float2(v10, v11);
            }
        }
    }
}

// ---------------------------------------------------------------------------
// KV chain from fp16 features: kv[b,h,i,j] = sum_s V[b,s,h,i] * K[b,s,h,j]
// fp16 -> fp32 conversion during smem fill; math unchanged (fp32).
// ---------------------------------------------------------------------------
__global__ void __launch_bounds__(256)
kv_kernel(const __half* __restrict__ K, const __half* __restrict__ V,
          float* __restrict__ kv, float* __restrict__ ksum) {
    const int bh = blockIdx.x;
    const int b  = bh / NHEADS;
    const int h  = bh % NHEADS;
    const int tid = threadIdx.x;
    const int ty  = tid >> 4;
    const int tx  = tid & 15;

    __shared__ float Ks[16][64];
    __shared__ float Vs[16][64];

    float acc[4][4];
#pragma unroll
    for (int i = 0; i < 4; i++)
#pragma unroll
        for (int j = 0; j < 4; j++) acc[i][j] = 0.0f;
    float ks_acc = 0.0f;

    const __half* Kbase = K + (size_t)b * S_LEN * DMODEL + h * DHEAD;
    const __half* Vbase = V + (size_t)b * S_LEN * DMODEL + h * DHEAD;
    const int s0 = blockIdx.y * (S_LEN / 8);

    // fill mapping: tid<128 -> K, tid>=128 -> V; r = (tid&127)>>3, c8 = (tid&7)*8
    const int fr  = (tid & 127) >> 3;
    const int fc8 = (tid & 7) * 8;
    const __half* fbase = (tid < 128 ? Kbase : Vbase);
    float (*fdst)[64] = (tid < 128 ? Ks : Vs);

    for (int s = s0; s < s0 + (S_LEN / 8); s += 16) {
        __syncthreads();
        {
            uint4 u = *(const uint4*)&fbase[(size_t)(s + fr) * DMODEL + fc8];
            const __half2* hp = (const __half2*)&u;
            float4 lo, hi;
            float2 f0 = __half22float2(hp[0]);
            float2 f1 = __half22float2(hp[1]);
            float2 f2 = __half22float2(hp[2]);
            float2 f3 = __half22float2(hp[3]);
            lo = make_float4(f0.x, f0.y, f1.x, f1.y);
            hi = make_float4(f2.x, f2.y, f3.x, f3.y);
            *(float4*)&fdst[fr][fc8]     = lo;
            *(float4*)&fdst[fr][fc8 + 4] = hi;
        }
        __syncthreads();
        if (tid < 64) {
#pragma unroll
            for (int ss = 0; ss < 16; ss++) ks_acc += Ks[ss][tid];
        }
#pragma unroll
        for (int ss = 0; ss < 16; ss++) {
            float vr[4], kr[4];
#pragma unroll
            for (int i = 0; i < 4; i++) vr[i] = Vs[ss][ty * 4 + i];
#pragma unroll
            for (int j = 0; j < 4; j++) kr[j] = Ks[ss][tx * 4 + j];
#pragma unroll
            for (int i = 0; i < 4; i++)
#pragma unroll
                for (int j = 0; j < 4; j++) acc[i][j] += vr[i] * kr[j];
        }
    }

    float* kvbh = kv + (size_t)bh * DHEAD * DHEAD;
#pragma unroll
    for (int i = 0; i < 4; i++)
#pragma unroll
        for (int j = 0; j < 4; j++)
            atomicAdd(&kvbh[(ty * 4 + i) * DHEAD + tx * 4 + j], acc[i][j]);
    if (tid < 64) atomicAdd(&ksum[bh * DHEAD + tid], ks_acc);
}

// ---------------------------------------------------------------------------
// Attention apply from fp16 Q features; output fp16 for the final GEMM
// ---------------------------------------------------------------------------
__global__ void __launch_bounds__(128)
attn_kernel(const __half* __restrict__ Q, const float* __restrict__ kv,
            const float* __restrict__ ksum, __half* __restrict__ attn) {
    const int h   = blockIdx.y;
    const int row = blockIdx.x * 128 + threadIdx.x;
    const int b   = row / S_LEN;

    __shared__ float kvs[64][64];
    __shared__ float kss[64];

    const float* kvsrc = kv + (size_t)(b * NHEADS + h) * DHEAD * DHEAD;
    for (int i = threadIdx.x; i < (DHEAD * DHEAD) / 4; i += 128)
        ((float4*)kvs)[i] = ((const float4*)kvsrc)[i];
    if (threadIdx.x < 64) kss[threadIdx.x] = ksum[(b * NHEADS + h) * DHEAD + threadIdx.x];
    __syncthreads();

    float q[64];
    {
        const __half* qp = Q + (size_t)row * DMODEL + h * DHEAD;
        uint4 raw[8];
#pragma unroll
        for (int i = 0; i < 8; i++) raw[i] = ((const uint4*)qp)[i];
        const __half2* hp = (const __half2*)raw;
#pragma unroll
        for (int j = 0; j < 32; j++) {
            float2 f = __half22float2(hp[j]);
            q[2 * j] = f.x; q[2 * j + 1] = f.y;
        }
    }

    float nd = 0.0f;
#pragma unroll
    for (int d = 0; d < 64; d++) nd += q[d] * kss[d];
    const float norm = 1.0f / (nd + 1e-6f);

    __half* op = attn + (size_t)row * DMODEL + h * DHEAD;
    for (int i0 = 0; i0 < 64; i0 += 4) {
        float out[4];
#pragma unroll
        for (int u = 0; u < 4; u++) {
            float s = 0.0f;
            const float4* kv4 = (const float4*)kvs[i0 + u];
#pragma unroll
            for (int d4 = 0; d4 < 16; d4++) {
                float4 kvv = kv4[d4];
                s += q[4*d4] * kvv.x + q[4*d4+1] * kvv.y
                   + q[4*d4+2] * kvv.z + q[4*d4+3] * kvv.w;
            }
            out[u] = s * norm;
        }
        __half2 h01 = __floats2half2_rn(out[0], out[1]);
        __half2 h23 = __floats2half2_rn(out[2], out[3]);
        *(__half2*)&op[i0]     = h01;
        *(__half2*)&op[i0 + 2] = h23;
    }
}

// ---------------------------------------------------------------------------
// Launch
// ---------------------------------------------------------------------------
extern "C" void kernel_launch(void* const* d_in, const int* in_sizes, int n_in,
                              void* d_out, int out_size) {
    const float* query = (const float*)d_in[0];
    const float* key_  = (const float*)d_in[1];
    const float* value = (const float*)d_in[2];
    const float* Wq = (const float*)d_in[3];
    const float* bq = (const float*)d_in[4];
    const float* Wk = (const float*)d_in[5];
    const float* bk = (const float*)d_in[6];
    const float* Wv = (const float*)d_in[7];
    const float* bv = (const float*)d_in[8];
    const float* Wo = (const float*)d_in[9];
    const float* bo = (const float*)d_in[10];
    float* out = (float*)d_out;

    float *kv, *ks;
    __half *hqf, *hkf, *hvf, *hq, *hk, *hv, *hattn, *hw;
    cudaGetSymbolAddress((void**)&kv,    g_kv);
    cudaGetSymbolAddress((void**)&ks,    g_ksum);
    cudaGetSymbolAddress((void**)&hqf,   g_hqf);
    cudaGetSymbolAddress((void**)&hkf,   g_hkf);
    cudaGetSymbolAddress((void**)&hvf,   g_hvf);
    cudaGetSymbolAddress((void**)&hq,    g_hq);
    cudaGetSymbolAddress((void**)&hk,    g_hk);
    cudaGetSymbolAddress((void**)&hv,    g_hv);
    cudaGetSymbolAddress((void**)&hattn, g_hattn);
    cudaGetSymbolAddress((void**)&hw,    g_hw);
    __half* hwq = hw;
    __half* hwk = hw + (size_t)DMODEL * DMODEL;
    __half* hwv = hw + (size_t)2 * DMODEL * DMODEL;
    __half* hwo = hw + (size_t)3 * DMODEL * DMODEL;

    static int smem_set = 0;
    if (!smem_set) {
        cudaFuncSetAttribute(gemm_fp16_kernel<1, 1>,
                             cudaFuncAttributeMaxDynamicSharedMemorySize, GEMM_SMEM_BYTES);
        cudaFuncSetAttribute(gemm_fp16_kernel<0, 1>,
                             cudaFuncAttributeMaxDynamicSharedMemorySize, GEMM_SMEM_BYTES);
        cudaFuncSetAttribute(gemm_fp16_kernel<0, 0>,
                             cudaFuncAttributeMaxDynamicSharedMemorySize, GEMM_SMEM_BYTES);
        smem_set = 1;
    }

    // fp16 pre-rounding passes
    const int N4_IN = (NROWS * DMODEL) / 4;
    const int N4_W  = (DMODEL * DMODEL) / 4;
    round_fp16_kernel<<<N4_IN / 256, 256>>>(query, hq, N4_IN);
    round_fp16_kernel<<<N4_IN / 256, 256>>>(key_,  hk, N4_IN);
    round_fp16_kernel<<<N4_IN / 256, 256>>>(value, hv, N4_IN);
    round_fp16_kernel<<<N4_W / 256, 256>>>(Wq, hwq, N4_W);
    round_fp16_kernel<<<N4_W / 256, 256>>>(Wk, hwk, N4_W);
    round_fp16_kernel<<<N4_W / 256, 256>>>(Wv, hwv, N4_W);
    round_fp16_kernel<<<N4_W / 256, 256>>>(Wo, hwo, N4_W);

    // zero accumulators for atomics
    zero_kernel<<<(BATCH * NHEADS * DHEAD * DHEAD + 255) / 256, 256>>>(kv, BATCH * NHEADS * DHEAD * DHEAD);
    zero_kernel<<<(BATCH * NHEADS * DHEAD + 255) / 256, 256>>>(ks, BATCH * NHEADS * DHEAD);

    dim3 gemm_grid(DMODEL / BN, NROWS / BM);  // (8, 256)
    gemm_fp16_kernel<1, 1><<<gemm_grid, 256, GEMM_SMEM_BYTES>>>(hq, hwq, bq, hqf);
    gemm_fp16_kernel<1, 1><<<gemm_grid, 256, GEMM_SMEM_BYTES>>>(hk, hwk, bk, hkf);
    gemm_fp16_kernel<0, 1><<<gemm_grid, 256, GEMM_SMEM_BYTES>>>(hv, hwv, bv, hvf);

    kv_kernel<<<dim3(BATCH * NHEADS, 8), 256>>>(hkf, hvf, kv, ks);

    attn_kernel<<<dim3(NROWS / 128, NHEADS), 128>>>(hqf, kv, ks, hattn);

    gemm_fp16_kernel<0, 0><<<gemm_grid, 256, GEMM_SMEM_BYTES>>>(hattn, hwo, bo, out);
}

// round 14
// speedup vs baseline: 1.1818x; 1.1420x over previous
#include <cuda_runtime.h>
#include <cuda_fp16.h>
#include <math.h>
#include <stdint.h>

#define S_LEN   8192
#define BATCH   4
#define DMODEL  1024
#define NROWS   (BATCH * S_LEN)   // 32768
#define NHEADS  16
#define DHEAD   64

// Scratch (device globals: allocation-free per harness rules)
__device__ __half g_hqf[(size_t)NROWS * DMODEL];  // fp16 Q features
__device__ __half g_hkf[(size_t)NROWS * DMODEL];  // fp16 K features
__device__ __half g_hvf[(size_t)NROWS * DMODEL];  // fp16 V features
__device__ __half g_hq[(size_t)NROWS * DMODEL];   // fp16-rounded inputs
__device__ __half g_hk[(size_t)NROWS * DMODEL];
__device__ __half g_hv[(size_t)NROWS * DMODEL];
__device__ __half g_hattn[(size_t)NROWS * DMODEL];
__device__ __half g_hw[4][DMODEL * DMODEL];       // fp16-rounded weights
__device__ float  g_kv[BATCH * NHEADS * DHEAD * DHEAD];   // [b,h,dv,dk]
__device__ float  g_ksum[BATCH * NHEADS * DHEAD];

// ---------------------------------------------------------------------------
// helpers
// ---------------------------------------------------------------------------
__device__ __forceinline__ void mma_fp16(float* c, const unsigned* a, const unsigned* b) {
    asm volatile(
        "mma.sync.aligned.m16n8k16.row.col.f32.f16.f16.f32 "
        "{%0,%1,%2,%3}, {%4,%5,%6,%7}, {%8,%9}, {%0,%1,%2,%3};"
        : "+f"(c[0]), "+f"(c[1]), "+f"(c[2]), "+f"(c[3])
        : "r"(a[0]), "r"(a[1]), "r"(a[2]), "r"(a[3]), "r"(b[0]), "r"(b[1]));
}

__device__ __forceinline__ void cp_async16(unsigned smem_addr, const void* gptr) {
    asm volatile("cp.async.cg.shared.global [%0], [%1], 16;"
                 :: "r"(smem_addr), "l"(gptr));
}
__device__ __forceinline__ void cp_commit() {
    asm volatile("cp.async.commit_group;");
}
template <int N>
__device__ __forceinline__ void cp_wait() {
    asm volatile("cp.async.wait_group %0;" :: "n"(N));
}

// ---------------------------------------------------------------------------
// Elementwise fp16 rounding pass (float4 -> 4 halves)
// ---------------------------------------------------------------------------
__global__ void round_fp16_kernel(const float* __restrict__ in,
                                  __half* __restrict__ out, int n4) {
    int i = blockIdx.x * blockDim.x + threadIdx.x;
    if (i < n4) {
        float4 v = ((const float4*)in)[i];
        __half2 h01 = __floats2half2_rn(v.x, v.y);
        __half2 h23 = __floats2half2_rn(v.z, v.w);
        __half2* o = (__half2*)(out + (size_t)i * 4);
        o[0] = h01; o[1] = h23;
    }
}

__global__ void zero_kernel(float* p, int n) {
    int i = blockIdx.x * blockDim.x + threadIdx.x;
    if (i < n) p[i] = 0.0f;
}

// ---------------------------------------------------------------------------
// fp16 GEMM (R10 proven config): C = A @ W^T + bias, optional elu+1.
// Output fp32 (OUTH=0) or fp16 (OUTH=1).
// 256 threads, 8 warps (2x4), warp tile 64x32.
// 3-stage cp.async pipeline, ONE barrier per k-chunk.
// ---------------------------------------------------------------------------
#define BM 128
#define BN 128
#define BKH 32                    // k halves per chunk
#define SPADH 48                  // halves per smem row (96B)
#define TILEH (BM * SPADH)        // 6144 halves = 12288 B
#define NSTAGE 3
#define GEMM_SMEM_BYTES (2 * NSTAGE * TILEH * 2)   // 73728 B

template <int EPI, int OUTH>
__global__ void __launch_bounds__(256, 2)
gemm_fp16_kernel(const __half* __restrict__ A, const __half* __restrict__ W,
                 const float* __restrict__ bias, void* __restrict__ Cv) {
    extern __shared__ __half sh[];            // [A0,A1,A2,B0,B1,B2]
    __half* Asm = sh;
    __half* Bsm = sh + NSTAGE * TILEH;

    const int tid  = threadIdx.x;
    const int lane = tid & 31;
    const int warp = tid >> 5;
    const int wm   = (warp & 1) * 64;
    const int wn   = (warp >> 1) * 32;
    const int m0   = blockIdx.y * BM;
    const int n0   = blockIdx.x * BN;
    const int g    = lane >> 2;
    const int tg   = lane & 3;

    unsigned sbase = (unsigned)__cvta_generic_to_shared(sh);

    float acc[4][4][4];
#pragma unroll
    for (int mt = 0; mt < 4; mt++)
#pragma unroll
        for (int nt = 0; nt < 4; nt++)
#pragma unroll
            for (int i = 0; i < 4; i++) acc[mt][nt][i] = 0.0f;

    const int r0  = tid >> 2;          // rows r0, r0+64
    const int kc  = (tid & 3) * 8;
    const __half* Ap = A + (size_t)(m0 + r0) * DMODEL + kc;
    const __half* Wp = W + (size_t)(n0 + r0) * DMODEL + kc;
    const unsigned a_d0 = sbase + (r0 * SPADH + kc) * 2;
    const unsigned a_d1 = sbase + ((r0 + 64) * SPADH + kc) * 2;
    const unsigned b_d0 = a_d0 + NSTAGE * TILEH * 2;
    const unsigned b_d1 = a_d1 + NSTAGE * TILEH * 2;

    const int NK = DMODEL / BKH;   // 32 chunks

    auto fill = [&](int c) {
        const unsigned so = (unsigned)(c % NSTAGE) * TILEH * 2;
        const __half* Apn = Ap + c * BKH;
        const __half* Wpn = Wp + c * BKH;
        cp_async16(a_d0 + so, Apn);
        cp_async16(a_d1 + so, Apn + (size_t)64 * DMODEL);
        cp_async16(b_d0 + so, Wpn);
        cp_async16(b_d1 + so, Wpn + (size_t)64 * DMODEL);
    };

    fill(0); cp_commit();
    fill(1); cp_commit();

    for (int kt = 0; kt < NK; kt++) {
        cp_wait<1>();
        __syncthreads();

        if (kt + 2 < NK) fill(kt + 2);
        cp_commit();

        const int buf = kt % NSTAGE;
        const __half* Ab = Asm + buf * TILEH;
        const __half* Bb = Bsm + buf * TILEH;
#pragma unroll
        for (int ks = 0; ks < 2; ks++) {
            const int kk = ks * 16 + 4 * tg;
            unsigned a[4][4], b[4][2];
#pragma unroll
            for (int mt = 0; mt < 4; mt++) {
                int base = (wm + mt * 16 + g) * SPADH + kk;
                uint2 lo = *(const uint2*)&Ab[base];
                uint2 hi = *(const uint2*)&Ab[base + 8 * SPADH];
                a[mt][0] = lo.x; a[mt][1] = hi.x; a[mt][2] = lo.y; a[mt][3] = hi.y;
            }
#pragma unroll
            for (int nt = 0; nt < 4; nt++) {
                uint2 bb = *(const uint2*)&Bb[(wn + nt * 8 + g) * SPADH + kk];
                b[nt][0] = bb.x; b[nt][1] = bb.y;
            }
#pragma unroll
            for (int mt = 0; mt < 4; mt++)
#pragma unroll
                for (int nt = 0; nt < 4; nt++)
                    mma_fp16(acc[mt][nt], a[mt], b[nt]);
        }
    }

    // epilogue: bias + optional elu(x)+1
#pragma unroll
    for (int mt = 0; mt < 4; mt++) {
#pragma unroll
        for (int nt = 0; nt < 4; nt++) {
            int row = m0 + wm + mt * 16 + g;
            int col = n0 + wn + nt * 8 + 2 * tg;
            float bv0 = bias[col];
            float bv1 = bias[col + 1];
            float v00 = acc[mt][nt][0] + bv0;
            float v01 = acc[mt][nt][1] + bv1;
            float v10 = acc[mt][nt][2] + bv0;
            float v11 = acc[mt][nt][3] + bv1;
            if (EPI) {
                v00 = (v00 > 0.0f) ? v00 + 1.0f : expf(v00);
                v01 = (v01 > 0.0f) ? v01 + 1.0f : expf(v01);
                v10 = (v10 > 0.0f) ? v10 + 1.0f : expf(v10);
                v11 = (v11 > 0.0f) ? v11 + 1.0f : expf(v11);
            }
            if (OUTH) {
                __half* C = (__half*)Cv;
                *(__half2*)&C[(size_t)row * DMODEL + col]       = __floats2half2_rn(v00, v01);
                *(__half2*)&C[(size_t)(row + 8) * DMODEL + col] = __floats2half2_rn(v10, v11);
            } else {
                float* C = (float*)Cv;
                *(float2*)&C[(size_t)row * DMODEL + col]       = make_float2(v00, v01);
                *(float2*)&C[(size_t)(row + 8) * DMODEL + col] = make_float2(v10, v11);
            }
        }
    }
}

// ---------------------------------------------------------------------------
// KV chain from fp16 features (unchanged from R12)
// ---------------------------------------------------------------------------
__global__ void __launch_bounds__(256)
kv_kernel(const __half* __restrict__ K, const __half* __restrict__ V,
          float* __restrict__ kv, float* __restrict__ ksum) {
    const int bh = blockIdx.x;
    const int b  = bh / NHEADS;
    const int h  = bh % NHEADS;
    const int tid = threadIdx.x;
    const int ty  = tid >> 4;
    const int tx  = tid & 15;

    __shared__ float Ks[16][64];
    __shared__ float Vs[16][64];

    float acc[4][4];
#pragma unroll
    for (int i = 0; i < 4; i++)
#pragma unroll
        for (int j = 0; j < 4; j++) acc[i][j] = 0.0f;
    float ks_acc = 0.0f;

    const __half* Kbase = K + (size_t)b * S_LEN * DMODEL + h * DHEAD;
    const __half* Vbase = V + (size_t)b * S_LEN * DMODEL + h * DHEAD;
    const int s0 = blockIdx.y * (S_LEN / 8);

    const int fr  = (tid & 127) >> 3;
    const int fc8 = (tid & 7) * 8;
    const __half* fbase = (tid < 128 ? Kbase : Vbase);
    float (*fdst)[64] = (tid < 128 ? Ks : Vs);

    for (int s = s0; s < s0 + (S_LEN / 8); s += 16) {
        __syncthreads();
        {
            uint4 u = *(const uint4*)&fbase[(size_t)(s + fr) * DMODEL + fc8];
            const __half2* hp = (const __half2*)&u;
            float2 f0 = __half22float2(hp[0]);
            float2 f1 = __half22float2(hp[1]);
            float2 f2 = __half22float2(hp[2]);
            float2 f3 = __half22float2(hp[3]);
            *(float4*)&fdst[fr][fc8]     = make_float4(f0.x, f0.y, f1.x, f1.y);
            *(float4*)&fdst[fr][fc8 + 4] = make_float4(f2.x, f2.y, f3.x, f3.y);
        }
        __syncthreads();
        if (tid < 64) {
#pragma unroll
            for (int ss = 0; ss < 16; ss++) ks_acc += Ks[ss][tid];
        }
#pragma unroll
        for (int ss = 0; ss < 16; ss++) {
            float vr[4], kr[4];
#pragma unroll
            for (int i = 0; i < 4; i++) vr[i] = Vs[ss][ty * 4 + i];
#pragma unroll
            for (int j = 0; j < 4; j++) kr[j] = Ks[ss][tx * 4 + j];
#pragma unroll
            for (int i = 0; i < 4; i++)
#pragma unroll
                for (int j = 0; j < 4; j++) acc[i][j] += vr[i] * kr[j];
        }
    }

    float* kvbh = kv + (size_t)bh * DHEAD * DHEAD;
#pragma unroll
    for (int i = 0; i < 4; i++)
#pragma unroll
        for (int j = 0; j < 4; j++)
            atomicAdd(&kvbh[(ty * 4 + i) * DHEAD + tx * 4 + j], acc[i][j]);
    if (tid < 64) atomicAdd(&ksum[bh * DHEAD + tid], ks_acc);
}

// ---------------------------------------------------------------------------
// Tensor-core attention apply:
//   out[t, h*64+i] = norm(t,h) * sum_d q[t,h,d] * kv[b,h,i,d]  -> fp16
// Block: 128 t-rows x 1 head, 128 threads (4 warps, each 2 m-tiles x 8 n-tiles).
// Fragment loads reuse the GEMM's proven k-reassignment LDS.64 pattern
// (APAD=80: conflict-free). Output staged in smem (OPAD=72) then stored
// coalesced as uint4.
// ---------------------------------------------------------------------------
#define APAD 80
#define OPAD 72

__global__ void __launch_bounds__(128)
attn_mma_kernel(const __half* __restrict__ Qf, const float* __restrict__ kv,
                const float* __restrict__ ksum, __half* __restrict__ attn) {
    const int h  = blockIdx.y;
    const int t0 = blockIdx.x * 128;
    const int b  = t0 / S_LEN;
    const int bh = b * NHEADS + h;
    const int tid  = threadIdx.x;
    const int lane = tid & 31;
    const int warp = tid >> 5;
    const int g    = lane >> 2;
    const int tg   = lane & 3;
    const int wm   = warp * 32;      // warp covers rows [wm, wm+32)

    __shared__ __half Qs[128 * APAD];   // 20 KB (reused as output staging)
    __shared__ __half Bs[64 * APAD];    // 10 KB
    __shared__ float  kss[64];
    __shared__ float  nrm[128];

    // Q tile [128][64] halves: 1024 uint4, 8 per thread (coalesced)
#pragma unroll
    for (int i = 0; i < 8; i++) {
        int idx = tid + 128 * i;
        int r = idx >> 3, c8 = (idx & 7) * 8;
        *(uint4*)&Qs[r * APAD + c8] =
            *(const uint4*)&Qf[(size_t)(t0 + r) * DMODEL + h * DHEAD + c8];
    }
    // kv tile [64][64] fp32 -> fp16 into smem: 1024 float4, 8 per thread
    const float* kvsrc = kv + (size_t)bh * DHEAD * DHEAD;
#pragma unroll
    for (int i = 0; i < 8; i++) {
        int idx = tid + 128 * i;
        int r = idx >> 4, c4 = (idx & 15) * 4;
        float4 v = *(const float4*)&kvsrc[r * DHEAD + c4];
        __half2* dst = (__half2*)&Bs[r * APAD + c4];
        dst[0] = __floats2half2_rn(v.x, v.y);
        dst[1] = __floats2half2_rn(v.z, v.w);
    }
    if (tid < 64) kss[tid] = ksum[bh * DHEAD + tid];
    __syncthreads();

    // norm: one thread per row
    {
        float nd = 0.0f;
        const __half2* qr = (const __half2*)&Qs[tid * APAD];
#pragma unroll
        for (int j = 0; j < 32; j++) {
            float2 f = __half22float2(qr[j]);
            nd += f.x * kss[2 * j] + f.y * kss[2 * j + 1];
        }
        nrm[tid] = 1.0f / (nd + 1e-6f);
    }
    __syncthreads();

    float acc[2][8][4];
#pragma unroll
    for (int mt = 0; mt < 2; mt++)
#pragma unroll
        for (int nt = 0; nt < 8; nt++)
#pragma unroll
            for (int i = 0; i < 4; i++) acc[mt][nt][i] = 0.0f;

#pragma unroll
    for (int ks = 0; ks < 4; ks++) {
        const int kk = ks * 16 + 4 * tg;
        unsigned a[2][4], bb[8][2];
#pragma unroll
        for (int mt = 0; mt < 2; mt++) {
            int base = (wm + mt * 16 + g) * APAD + kk;
            uint2 lo = *(const uint2*)&Qs[base];
            uint2 hi = *(const uint2*)&Qs[base + 8 * APAD];
            a[mt][0] = lo.x; a[mt][1] = hi.x; a[mt][2] = lo.y; a[mt][3] = hi.y;
        }
#pragma unroll
        for (int nt = 0; nt < 8; nt++) {
            uint2 bv = *(const uint2*)&Bs[(nt * 8 + g) * APAD + kk];
            bb[nt][0] = bv.x; bb[nt][1] = bv.y;
        }
#pragma unroll
        for (int mt = 0; mt < 2; mt++)
#pragma unroll
            for (int nt = 0; nt < 8; nt++)
                mma_fp16(acc[mt][nt], a[mt], bb[nt]);
    }

    // stage scaled fp16 output in smem (reuse Qs; 128 x OPAD)
    __syncthreads();
    __half* Os = Qs;
#pragma unroll
    for (int mt = 0; mt < 2; mt++) {
        int row0 = wm + mt * 16 + g;
        float n0 = nrm[row0];
        float n1 = nrm[row0 + 8];
#pragma unroll
        for (int nt = 0; nt < 8; nt++) {
            int col = nt * 8 + 2 * tg;
            *(__half2*)&Os[row0 * OPAD + col] =
                __floats2half2_rn(acc[mt][nt][0] * n0, acc[mt][nt][1] * n0);
            *(__half2*)&Os[(row0 + 8) * OPAD + col] =
                __floats2half2_rn(acc[mt][nt][2] * n1, acc[mt][nt][3] * n1);
        }
    }
    __syncthreads();

    // coalesced store: 128 rows x 64 halves = 1024 uint4, 8 per thread
#pragma unroll
    for (int i = 0; i < 8; i++) {
        int idx = tid + 128 * i;
        int r = idx >> 3, c8 = (idx & 7) * 8;
        uint4 v = *(const uint4*)&Os[r * OPAD + c8];
        *(uint4*)&attn[(size_t)(t0 + r) * DMODEL + h * DHEAD + c8] = v;
    }
}

// ---------------------------------------------------------------------------
// Launch
// ---------------------------------------------------------------------------
extern "C" void kernel_launch(void* const* d_in, const int* in_sizes, int n_in,
                              void* d_out, int out_size) {
    const float* query = (const float*)d_in[0];
    const float* key_  = (const float*)d_in[1];
    const float* value = (const float*)d_in[2];
    const float* Wq = (const float*)d_in[3];
    const float* bq = (const float*)d_in[4];
    const float* Wk = (const float*)d_in[5];
    const float* bk = (const float*)d_in[6];
    const float* Wv = (const float*)d_in[7];
    const float* bv = (const float*)d_in[8];
    const float* Wo = (const float*)d_in[9];
    const float* bo = (const float*)d_in[10];
    float* out = (float*)d_out;

    float *kv, *ks;
    __half *hqf, *hkf, *hvf, *hq, *hk, *hv, *hattn, *hw;
    cudaGetSymbolAddress((void**)&kv,    g_kv);
    cudaGetSymbolAddress((void**)&ks,    g_ksum);
    cudaGetSymbolAddress((void**)&hqf,   g_hqf);
    cudaGetSymbolAddress((void**)&hkf,   g_hkf);
    cudaGetSymbolAddress((void**)&hvf,   g_hvf);
    cudaGetSymbolAddress((void**)&hq,    g_hq);
    cudaGetSymbolAddress((void**)&hk,    g_hk);
    cudaGetSymbolAddress((void**)&hv,    g_hv);
    cudaGetSymbolAddress((void**)&hattn, g_hattn);
    cudaGetSymbolAddress((void**)&hw,    g_hw);
    __half* hwq = hw;
    __half* hwk = hw + (size_t)DMODEL * DMODEL;
    __half* hwv = hw + (size_t)2 * DMODEL * DMODEL;
    __half* hwo = hw + (size_t)3 * DMODEL * DMODEL;

    static int smem_set = 0;
    if (!smem_set) {
        cudaFuncSetAttribute(gemm_fp16_kernel<1, 1>,
                             cudaFuncAttributeMaxDynamicSharedMemorySize, GEMM_SMEM_BYTES);
        cudaFuncSetAttribute(gemm_fp16_kernel<0, 1>,
                             cudaFuncAttributeMaxDynamicSharedMemorySize, GEMM_SMEM_BYTES);
        cudaFuncSetAttribute(gemm_fp16_kernel<0, 0>,
                             cudaFuncAttributeMaxDynamicSharedMemorySize, GEMM_SMEM_BYTES);
        smem_set = 1;
    }

    // fp16 pre-rounding passes
    const int N4_IN = (NROWS * DMODEL) / 4;
    const int N4_W  = (DMODEL * DMODEL) / 4;
    round_fp16_kernel<<<N4_IN / 256, 256>>>(query, hq, N4_IN);
    round_fp16_kernel<<<N4_IN / 256, 256>>>(key_,  hk, N4_IN);
    round_fp16_kernel<<<N4_IN / 256, 256>>>(value, hv, N4_IN);
    round_fp16_kernel<<<N4_W / 256, 256>>>(Wq, hwq, N4_W);
    round_fp16_kernel<<<N4_W / 256, 256>>>(Wk, hwk, N4_W);
    round_fp16_kernel<<<N4_W / 256, 256>>>(Wv, hwv, N4_W);
    round_fp16_kernel<<<N4_W / 256, 256>>>(Wo, hwo, N4_W);

    // zero accumulators for atomics
    zero_kernel<<<(BATCH * NHEADS * DHEAD * DHEAD + 255) / 256, 256>>>(kv, BATCH * NHEADS * DHEAD * DHEAD);
    zero_kernel<<<(BATCH * NHEADS * DHEAD + 255) / 256, 256>>>(ks, BATCH * NHEADS * DHEAD);

    dim3 gemm_grid(DMODEL / BN, NROWS / BM);  // (8, 256)
    gemm_fp16_kernel<1, 1><<<gemm_grid, 256, GEMM_SMEM_BYTES>>>(hq, hwq, bq, hqf);
    gemm_fp16_kernel<1, 1><<<gemm_grid, 256, GEMM_SMEM_BYTES>>>(hk, hwk, bk, hkf);
    gemm_fp16_kernel<0, 1><<<gemm_grid, 256, GEMM_SMEM_BYTES>>>(hv, hwv, bv, hvf);

    kv_kernel<<<dim3(BATCH * NHEADS, 8), 256>>>(hkf, hvf, kv, ks);

    attn_mma_kernel<<<dim3(NROWS / 128, NHEADS), 128>>>(hqf, kv, ks, hattn);

    gemm_fp16_kernel<0, 0><<<gemm_grid, 256, GEMM_SMEM_BYTES>>>(hattn, hwo, bo, out);
}

// round 15
// speedup vs baseline: 1.2620x; 1.0679x over previous
#include <cuda_runtime.h>
#include <cuda_fp16.h>
#include <math.h>
#include <stdint.h>

#define S_LEN   8192
#define BATCH   4
#define DMODEL  1024
#define NROWS   (BATCH * S_LEN)   // 32768
#define NHEADS  16
#define DHEAD   64

// Scratch (device globals: allocation-free per harness rules)
__device__ __half g_hqf[(size_t)NROWS * DMODEL];  // fp16 Q features (token-major)
__device__ __half g_hkt[(size_t)NROWS * DMODEL];  // fp16 K features TRANSPOSED [b*1024+feat][s]
__device__ __half g_hvt[(size_t)NROWS * DMODEL];  // fp16 V features TRANSPOSED
__device__ __half g_hq[(size_t)NROWS * DMODEL];   // fp16-rounded inputs
__device__ __half g_hk[(size_t)NROWS * DMODEL];
__device__ __half g_hv[(size_t)NROWS * DMODEL];
__device__ __half g_hattn[(size_t)NROWS * DMODEL];
__device__ __half g_hw[4][DMODEL * DMODEL];       // fp16-rounded weights
__device__ float  g_kv[BATCH * NHEADS * DHEAD * DHEAD];   // [b,h,dv,dk]
__device__ float  g_ksum[BATCH * NHEADS * DHEAD];

// ---------------------------------------------------------------------------
// helpers
// ---------------------------------------------------------------------------
__device__ __forceinline__ void mma_fp16(float* c, const unsigned* a, const unsigned* b) {
    asm volatile(
        "mma.sync.aligned.m16n8k16.row.col.f32.f16.f16.f32 "
        "{%0,%1,%2,%3}, {%4,%5,%6,%7}, {%8,%9}, {%0,%1,%2,%3};"
        : "+f"(c[0]), "+f"(c[1]), "+f"(c[2]), "+f"(c[3])
        : "r"(a[0]), "r"(a[1]), "r"(a[2]), "r"(a[3]), "r"(b[0]), "r"(b[1]));
}

__device__ __forceinline__ void cp_async16(unsigned smem_addr, const void* gptr) {
    asm volatile("cp.async.cg.shared.global [%0], [%1], 16;"
                 :: "r"(smem_addr), "l"(gptr));
}
__device__ __forceinline__ void cp_commit() {
    asm volatile("cp.async.commit_group;");
}
template <int N>
__device__ __forceinline__ void cp_wait() {
    asm volatile("cp.async.wait_group %0;" :: "n"(N));
}

// ---------------------------------------------------------------------------
// Elementwise fp16 rounding pass (float4 -> 4 halves)
// ---------------------------------------------------------------------------
__global__ void round_fp16_kernel(const float* __restrict__ in,
                                  __half* __restrict__ out, int n4) {
    int i = blockIdx.x * blockDim.x + threadIdx.x;
    if (i < n4) {
        float4 v = ((const float4*)in)[i];
        __half2 h01 = __floats2half2_rn(v.x, v.y);
        __half2 h23 = __floats2half2_rn(v.z, v.w);
        __half2* o = (__half2*)(out + (size_t)i * 4);
        o[0] = h01; o[1] = h23;
    }
}

__global__ void zero_kernel(float* p, int n) {
    int i = blockIdx.x * blockDim.x + threadIdx.x;
    if (i < n) p[i] = 0.0f;
}

// ---------------------------------------------------------------------------
// fp16 GEMM: C = A @ W^T + bias, optional elu+1.
// OUTMODE: 0 = fp32 token-major, 1 = fp16 token-major,
//          2 = fp16 TRANSPOSED: Ct[(b*1024 + col)][s], s contiguous
// 256 threads, 8 warps (2x4), warp tile 64x32, 3-stage cp.async pipeline.
// ---------------------------------------------------------------------------
#define BM 128
#define BN 128
#define BKH 32                    // k halves per chunk
#define SPADH 48                  // halves per smem row (96B)
#define TILEH (BM * SPADH)        // 6144 halves = 12288 B
#define NSTAGE 3
#define GEMM_SMEM_BYTES (2 * NSTAGE * TILEH * 2)   // 73728 B
#define CPAD 130                  // halves per staging row

template <int EPI, int OUTMODE>
__global__ void __launch_bounds__(256, 2)
gemm_fp16_kernel(const __half* __restrict__ A, const __half* __restrict__ W,
                 const float* __restrict__ bias, void* __restrict__ Cv) {
    extern __shared__ __half sh[];            // [A0,A1,A2,B0,B1,B2]
    __half* Asm = sh;
    __half* Bsm = sh + NSTAGE * TILEH;

    const int tid  = threadIdx.x;
    const int lane = tid & 31;
    const int warp = tid >> 5;
    const int wm   = (warp & 1) * 64;
    const int wn   = (warp >> 1) * 32;
    const int m0   = blockIdx.y * BM;
    const int n0   = blockIdx.x * BN;
    const int g    = lane >> 2;
    const int tg   = lane & 3;

    unsigned sbase = (unsigned)__cvta_generic_to_shared(sh);

    float acc[4][4][4];
#pragma unroll
    for (int mt = 0; mt < 4; mt++)
#pragma unroll
        for (int nt = 0; nt < 4; nt++)
#pragma unroll
            for (int i = 0; i < 4; i++) acc[mt][nt][i] = 0.0f;

    const int r0  = tid >> 2;          // rows r0, r0+64
    const int kc  = (tid & 3) * 8;
    const __half* Ap = A + (size_t)(m0 + r0) * DMODEL + kc;
    const __half* Wp = W + (size_t)(n0 + r0) * DMODEL + kc;
    const unsigned a_d0 = sbase + (r0 * SPADH + kc) * 2;
    const unsigned a_d1 = sbase + ((r0 + 64) * SPADH + kc) * 2;
    const unsigned b_d0 = a_d0 + NSTAGE * TILEH * 2;
    const unsigned b_d1 = a_d1 + NSTAGE * TILEH * 2;

    const int NK = DMODEL / BKH;   // 32 chunks

    auto fill = [&](int c) {
        const unsigned so = (unsigned)(c % NSTAGE) * TILEH * 2;
        const __half* Apn = Ap + c * BKH;
        const __half* Wpn = Wp + c * BKH;
        cp_async16(a_d0 + so, Apn);
        cp_async16(a_d1 + so, Apn + (size_t)64 * DMODEL);
        cp_async16(b_d0 + so, Wpn);
        cp_async16(b_d1 + so, Wpn + (size_t)64 * DMODEL);
    };

    fill(0); cp_commit();
    fill(1); cp_commit();

    for (int kt = 0; kt < NK; kt++) {
        cp_wait<1>();
        __syncthreads();

        if (kt + 2 < NK) fill(kt + 2);
        cp_commit();

        const int buf = kt % NSTAGE;
        const __half* Ab = Asm + buf * TILEH;
        const __half* Bb = Bsm + buf * TILEH;
#pragma unroll
        for (int ks = 0; ks < 2; ks++) {
            const int kk = ks * 16 + 4 * tg;
            unsigned a[4][4], b[4][2];
#pragma unroll
            for (int mt = 0; mt < 4; mt++) {
                int base = (wm + mt * 16 + g) * SPADH + kk;
                uint2 lo = *(const uint2*)&Ab[base];
                uint2 hi = *(const uint2*)&Ab[base + 8 * SPADH];
                a[mt][0] = lo.x; a[mt][1] = hi.x; a[mt][2] = lo.y; a[mt][3] = hi.y;
            }
#pragma unroll
            for (int nt = 0; nt < 4; nt++) {
                uint2 bb = *(const uint2*)&Bb[(wn + nt * 8 + g) * SPADH + kk];
                b[nt][0] = bb.x; b[nt][1] = bb.y;
            }
#pragma unroll
            for (int mt = 0; mt < 4; mt++)
#pragma unroll
                for (int nt = 0; nt < 4; nt++)
                    mma_fp16(acc[mt][nt], a[mt], b[nt]);
        }
    }

    if (OUTMODE == 2) __syncthreads();   // mainloop smem reads done before restaging

    // epilogue: bias + optional elu(x)+1
#pragma unroll
    for (int mt = 0; mt < 4; mt++) {
#pragma unroll
        for (int nt = 0; nt < 4; nt++) {
            int row = m0 + wm + mt * 16 + g;
            int col = n0 + wn + nt * 8 + 2 * tg;
            float bv0 = bias[col];
            float bv1 = bias[col + 1];
            float v00 = acc[mt][nt][0] + bv0;
            float v01 = acc[mt][nt][1] + bv1;
            float v10 = acc[mt][nt][2] + bv0;
            float v11 = acc[mt][nt][3] + bv1;
            if (EPI) {
                v00 = (v00 > 0.0f) ? v00 + 1.0f : expf(v00);
                v01 = (v01 > 0.0f) ? v01 + 1.0f : expf(v01);
                v10 = (v10 > 0.0f) ? v10 + 1.0f : expf(v10);
                v11 = (v11 > 0.0f) ? v11 + 1.0f : expf(v11);
            }
            if (OUTMODE == 0) {
                float* C = (float*)Cv;
                *(float2*)&C[(size_t)row * DMODEL + col]       = make_float2(v00, v01);
                *(float2*)&C[(size_t)(row + 8) * DMODEL + col] = make_float2(v10, v11);
            } else if (OUTMODE == 1) {
                __half* C = (__half*)Cv;
                *(__half2*)&C[(size_t)row * DMODEL + col]       = __floats2half2_rn(v00, v01);
                *(__half2*)&C[(size_t)(row + 8) * DMODEL + col] = __floats2half2_rn(v10, v11);
            } else {
                // stage into smem (tile-local coords) for transposed store
                int lr = wm + mt * 16 + g;
                int lc = wn + nt * 8 + 2 * tg;
                *(__half2*)&sh[lr * CPAD + lc]       = __floats2half2_rn(v00, v01);
                *(__half2*)&sh[(lr + 8) * CPAD + lc] = __floats2half2_rn(v10, v11);
            }
        }
    }

    if (OUTMODE == 2) {
        __syncthreads();
        __half* Ct = (__half*)Cv;
        const int b    = m0 >> 13;        // m0 / 8192
        const int srow = m0 & 8191;
        // 128 cols x 16 m-blocks of 8 = 2048 uint4 outputs, 8 per thread
#pragma unroll
        for (int i = 0; i < 8; i++) {
            int slot = tid + 256 * i;
            int n  = slot & 127;
            int mb = slot >> 7;           // 0..15
            union { __half h[8]; uint4 u; } tmp;
#pragma unroll
            for (int j = 0; j < 8; j++)
                tmp.h[j] = sh[(mb * 8 + j) * CPAD + n];
            *(uint4*)&Ct[(size_t)(b * 1024 + n0 + n) * S_LEN + srow + mb * 8] = tmp.u;
        }
    }
}

// ---------------------------------------------------------------------------
// Tensor-core KV chain from TRANSPOSED features:
//   kv[i][j] += sum_s Vt[i][s] * Kt[j][s];  ksum[j] += sum_s Kt[j][s]
// grid (64 bh, 16 s-splits of 512). 256 threads, 8 warps:
//   wm=(warp&3)*16 (m-tile), wn=(warp>>2)*32 (4 n-tiles).
// Same fragment pattern / pipeline as the main GEMM.
// ---------------------------------------------------------------------------
#define KVROWS 128                 // 64 Vt rows + 64 Kt rows per stage
#define KVTILEH (KVROWS * SPADH)   // 6144 halves per stage
#define NSPLIT 16

__global__ void __launch_bounds__(256)
kv_mma_kernel(const __half* __restrict__ Kt, const __half* __restrict__ Vt,
              float* __restrict__ kv, float* __restrict__ ksum) {
    __shared__ __half sh[NSTAGE * KVTILEH];   // 36864 B

    const int bh = blockIdx.x;
    const int b  = bh >> 4;
    const int h  = bh & 15;
    const int s0 = blockIdx.y * (S_LEN / NSPLIT);   // 512-wide split
    const int tid  = threadIdx.x;
    const int lane = tid & 31;
    const int warp = tid >> 5;
    const int g    = lane >> 2;
    const int tg   = lane & 3;
    const int wm   = (warp & 3) * 16;
    const int wn   = (warp >> 2) * 32;

    const __half* VtB = Vt + (size_t)(b * 1024 + h * 64) * S_LEN + s0;
    const __half* KtB = Kt + (size_t)(b * 1024 + h * 64) * S_LEN + s0;

    unsigned sbase = (unsigned)__cvta_generic_to_shared(sh);

    // fill mapping: op = tid>>7 (0=Vt rows 0..63, 1=Kt rows 64..127)
    const int fop  = tid >> 7;
    const int fidx = tid & 127;
    const __half* fb = fop ? KtB : VtB;

    auto fill = [&](int c) {
        const unsigned so = (unsigned)(c % NSTAGE) * KVTILEH * 2;
#pragma unroll
        for (int i = 0; i < 2; i++) {
            int slot = fidx + 128 * i;        // 0..255
            int r  = slot >> 2;               // 0..63
            int kc = (slot & 3) * 8;
            cp_async16(sbase + so + ((fop * 64 + r) * SPADH + kc) * 2,
                       fb + (size_t)r * S_LEN + c * BKH + kc);
        }
    };

    float acc[4][4];
#pragma unroll
    for (int nt = 0; nt < 4; nt++)
#pragma unroll
        for (int i = 0; i < 4; i++) acc[nt][i] = 0.0f;

    const int NC = (S_LEN / NSPLIT) / BKH;   // 16 chunks
    fill(0); cp_commit();
    fill(1); cp_commit();

    for (int c = 0; c < NC; c++) {
        cp_wait<1>();
        __syncthreads();
        if (c + 2 < NC) fill(c + 2);
        cp_commit();

        const __half* Sb = sh + (c % NSTAGE) * KVTILEH;
#pragma unroll
        for (int ks = 0; ks < 2; ks++) {
            const int kk = ks * 16 + 4 * tg;
            unsigned a[4], bb[4][2];
            {
                int base = (wm + g) * SPADH + kk;
                uint2 lo = *(const uint2*)&Sb[base];
                uint2 hi = *(const uint2*)&Sb[base + 8 * SPADH];
                a[0] = lo.x; a[1] = hi.x; a[2] = lo.y; a[3] = hi.y;
            }
#pragma unroll
            for (int nt = 0; nt < 4; nt++) {
                uint2 bv = *(const uint2*)&Sb[(64 + wn + nt * 8 + g) * SPADH + kk];
                bb[nt][0] = bv.x; bb[nt][1] = bv.y;
            }
#pragma unroll
            for (int nt = 0; nt < 4; nt++)
                mma_fp16(acc[nt], a, bb[nt]);
        }
        __syncthreads();
    }

    // accumulate kv
    float* kvbh = kv + (size_t)bh * DHEAD * DHEAD;
    const int row0 = wm + g;
#pragma unroll
    for (int nt = 0; nt < 4; nt++) {
        int col = wn + nt * 8 + 2 * tg;
        atomicAdd(&kvbh[row0 * DHEAD + col],           acc[nt][0]);
        atomicAdd(&kvbh[row0 * DHEAD + col + 1],       acc[nt][1]);
        atomicAdd(&kvbh[(row0 + 8) * DHEAD + col],     acc[nt][2]);
        atomicAdd(&kvbh[(row0 + 8) * DHEAD + col + 1], acc[nt][3]);
    }

    // ksum: row sums of Kt over this split (cache-hot)
    {
        int j = tid >> 2;            // 0..63
        int q = tid & 3;
        const __half* kr = KtB + (size_t)j * S_LEN + q * 128;
        float s = 0.0f;
#pragma unroll
        for (int u = 0; u < 16; u++) {
            uint4 raw = *(const uint4*)&kr[u * 8];
            const __half2* hp = (const __half2*)&raw;
#pragma unroll
            for (int p = 0; p < 4; p++) {
                float2 f = __half22float2(hp[p]);
                s += f.x + f.y;
            }
        }
        s += __shfl_down_sync(0xFFFFFFFF, s, 1);
        s += __shfl_down_sync(0xFFFFFFFF, s, 2);
        if (q == 0) atomicAdd(&ksum[bh * DHEAD + j], s);
    }
}

// ---------------------------------------------------------------------------
// Tensor-core attention apply (R14 proven):
//   out[t, h*64+i] = norm(t,h) * sum_d q[t,h,d] * kv[b,h,i,d]  -> fp16
// ---------------------------------------------------------------------------
#define APAD 80
#define OPAD 72

__global__ void __launch_bounds__(128)
attn_mma_kernel(const __half* __restrict__ Qf, const float* __restrict__ kv,
                const float* __restrict__ ksum, __half* __restrict__ attn) {
    const int h  = blockIdx.y;
    const int t0 = blockIdx.x * 128;
    const int b  = t0 / S_LEN;
    const int bh = b * NHEADS + h;
    const int tid  = threadIdx.x;
    const int lane = tid & 31;
    const int warp = tid >> 5;
    const int g    = lane >> 2;
    const int tg   = lane & 3;
    const int wm   = warp * 32;

    __shared__ __half Qs[128 * APAD];
    __shared__ __half Bs[64 * APAD];
    __shared__ float  kss[64];
    __shared__ float  nrm[128];

#pragma unroll
    for (int i = 0; i < 8; i++) {
        int idx = tid + 128 * i;
        int r = idx >> 3, c8 = (idx & 7) * 8;
        *(uint4*)&Qs[r * APAD + c8] =
            *(const uint4*)&Qf[(size_t)(t0 + r) * DMODEL + h * DHEAD + c8];
    }
    const float* kvsrc = kv + (size_t)bh * DHEAD * DHEAD;
#pragma unroll
    for (int i = 0; i < 8; i++) {
        int idx = tid + 128 * i;
        int r = idx >> 4, c4 = (idx & 15) * 4;
        float4 v = *(const float4*)&kvsrc[r * DHEAD + c4];
        __half2* dst = (__half2*)&Bs[r * APAD + c4];
        dst[0] = __floats2half2_rn(v.x, v.y);
        dst[1] = __floats2half2_rn(v.z, v.w);
    }
    if (tid < 64) kss[tid] = ksum[bh * DHEAD + tid];
    __syncthreads();

    {
        float nd = 0.0f;
        const __half2* qr = (const __half2*)&Qs[tid * APAD];
#pragma unroll
        for (int j = 0; j < 32; j++) {
            float2 f = __half22float2(qr[j]);
            nd += f.x * kss[2 * j] + f.y * kss[2 * j + 1];
        }
        nrm[tid] = 1.0f / (nd + 1e-6f);
    }
    __syncthreads();

    float acc[2][8][4];
#pragma unroll
    for (int mt = 0; mt < 2; mt++)
#pragma unroll
        for (int nt = 0; nt < 8; nt++)
#pragma unroll
            for (int i = 0; i < 4; i++) acc[mt][nt][i] = 0.0f;

#pragma unroll
    for (int ks = 0; ks < 4; ks++) {
        const int kk = ks * 16 + 4 * tg;
        unsigned a[2][4], bb[8][2];
#pragma unroll
        for (int mt = 0; mt < 2; mt++) {
            int base = (wm + mt * 16 + g) * APAD + kk;
            uint2 lo = *(const uint2*)&Qs[base];
            uint2 hi = *(const uint2*)&Qs[base + 8 * APAD];
            a[mt][0] = lo.x; a[mt][1] = hi.x; a[mt][2] = lo.y; a[mt][3] = hi.y;
        }
#pragma unroll
        for (int nt = 0; nt < 8; nt++) {
            uint2 bv = *(const uint2*)&Bs[(nt * 8 + g) * APAD + kk];
            bb[nt][0] = bv.x; bb[nt][1] = bv.y;
        }
#pragma unroll
        for (int mt = 0; mt < 2; mt++)
#pragma unroll
            for (int nt = 0; nt < 8; nt++)
                mma_fp16(acc[mt][nt], a[mt], bb[nt]);
    }

    __syncthreads();
    __half* Os = Qs;
#pragma unroll
    for (int mt = 0; mt < 2; mt++) {
        int row0 = wm + mt * 16 + g;
        float n0 = nrm[row0];
        float n1 = nrm[row0 + 8];
#pragma unroll
        for (int nt = 0; nt < 8; nt++) {
            int col = nt * 8 + 2 * tg;
            *(__half2*)&Os[row0 * OPAD + col] =
                __floats2half2_rn(acc[mt][nt][0] * n0, acc[mt][nt][1] * n0);
            *(__half2*)&Os[(row0 + 8) * OPAD + col] =
                __floats2half2_rn(acc[mt][nt][2] * n1, acc[mt][nt][3] * n1);
        }
    }
    __syncthreads();

#pragma unroll
    for (int i = 0; i < 8; i++) {
        int idx = tid + 128 * i;
        int r = idx >> 3, c8 = (idx & 7) * 8;
        uint4 v = *(const uint4*)&Os[r * OPAD + c8];
        *(uint4*)&attn[(size_t)(t0 + r) * DMODEL + h * DHEAD + c8] = v;
    }
}

// ---------------------------------------------------------------------------
// Launch
// ---------------------------------------------------------------------------
extern "C" void kernel_launch(void* const* d_in, const int* in_sizes, int n_in,
                              void* d_out, int out_size) {
    const float* query = (const float*)d_in[0];
    const float* key_  = (const float*)d_in[1];
    const float* value = (const float*)d_in[2];
    const float* Wq = (const float*)d_in[3];
    const float* bq = (const float*)d_in[4];
    const float* Wk = (const float*)d_in[5];
    const float* bk = (const float*)d_in[6];
    const float* Wv = (const float*)d_in[7];
    const float* bv = (const float*)d_in[8];
    const float* Wo = (const float*)d_in[9];
    const float* bo = (const float*)d_in[10];
    float* out = (float*)d_out;

    float *kv, *ks;
    __half *hqf, *hkt, *hvt, *hq, *hk, *hv, *hattn, *hw;
    cudaGetSymbolAddress((void**)&kv,    g_kv);
    cudaGetSymbolAddress((void**)&ks,    g_ksum);
    cudaGetSymbolAddress((void**)&hqf,   g_hqf);
    cudaGetSymbolAddress((void**)&hkt,   g_hkt);
    cudaGetSymbolAddress((void**)&hvt,   g_hvt);
    cudaGetSymbolAddress((void**)&hq,    g_hq);
    cudaGetSymbolAddress((void**)&hk,    g_hk);
    cudaGetSymbolAddress((void**)&hv,    g_hv);
    cudaGetSymbolAddress((void**)&hattn, g_hattn);
    cudaGetSymbolAddress((void**)&hw,    g_hw);
    __half* hwq = hw;
    __half* hwk = hw + (size_t)DMODEL * DMODEL;
    __half* hwv = hw + (size_t)2 * DMODEL * DMODEL;
    __half* hwo = hw + (size_t)3 * DMODEL * DMODEL;

    static int smem_set = 0;
    if (!smem_set) {
        cudaFuncSetAttribute(gemm_fp16_kernel<1, 1>,
                             cudaFuncAttributeMaxDynamicSharedMemorySize, GEMM_SMEM_BYTES);
        cudaFuncSetAttribute(gemm_fp16_kernel<1, 2>,
                             cudaFuncAttributeMaxDynamicSharedMemorySize, GEMM_SMEM_BYTES);
        cudaFuncSetAttribute(gemm_fp16_kernel<0, 2>,
                             cudaFuncAttributeMaxDynamicSharedMemorySize, GEMM_SMEM_BYTES);
        cudaFuncSetAttribute(gemm_fp16_kernel<0, 0>,
                             cudaFuncAttributeMaxDynamicSharedMemorySize, GEMM_SMEM_BYTES);
        smem_set = 1;
    }

    // fp16 pre-rounding passes
    const int N4_IN = (NROWS * DMODEL) / 4;
    const int N4_W  = (DMODEL * DMODEL) / 4;
    round_fp16_kernel<<<N4_IN / 256, 256>>>(query, hq, N4_IN);
    round_fp16_kernel<<<N4_IN / 256, 256>>>(key_,  hk, N4_IN);
    round_fp16_kernel<<<N4_IN / 256, 256>>>(value, hv, N4_IN);
    round_fp16_kernel<<<N4_W / 256, 256>>>(Wq, hwq, N4_W);
    round_fp16_kernel<<<N4_W / 256, 256>>>(Wk, hwk, N4_W);
    round_fp16_kernel<<<N4_W / 256, 256>>>(Wv, hwv, N4_W);
    round_fp16_kernel<<<N4_W / 256, 256>>>(Wo, hwo, N4_W);

    // zero accumulators for atomics
    zero_kernel<<<(BATCH * NHEADS * DHEAD * DHEAD + 255) / 256, 256>>>(kv, BATCH * NHEADS * DHEAD * DHEAD);
    zero_kernel<<<(BATCH * NHEADS * DHEAD + 255) / 256, 256>>>(ks, BATCH * NHEADS * DHEAD);

    dim3 gemm_grid(DMODEL / BN, NROWS / BM);  // (8, 256)
    gemm_fp16_kernel<1, 1><<<gemm_grid, 256, GEMM_SMEM_BYTES>>>(hq, hwq, bq, hqf);   // Q normal fp16
    gemm_fp16_kernel<1, 2><<<gemm_grid, 256, GEMM_SMEM_BYTES>>>(hk, hwk, bk, hkt);   // K transposed
    gemm_fp16_kernel<0, 2><<<gemm_grid, 256, GEMM_SMEM_BYTES>>>(hv, hwv, bv, hvt);   // V transposed

    kv_mma_kernel<<<dim3(BATCH * NHEADS, NSPLIT), 256>>>(hkt, hvt, kv, ks);

    attn_mma_kernel<<<dim3(NROWS / 128, NHEADS), 128>>>(hqf, kv, ks, hattn);

    gemm_fp16_kernel<0, 0><<<gemm_grid, 256, GEMM_SMEM_BYTES>>>(hattn, hwo, bo, out);
}